// round 1
// baseline (speedup 1.0000x reference)
#include <cuda_runtime.h>

// ---------------------------------------------------------------------------
// yolo_detect_target: only the first num = int(N*0.02) rows can contribute
// (cumprod-of-ok early-break semantics). Fallback global max is dead for this
// input but implemented behind a flag early-exit.
// ---------------------------------------------------------------------------

#define CONF_T 0.25f
#define MAX_NUM (1 << 20)   // capacity for per-row values (num = 20000 here)

__device__ float    g_vals[MAX_NUM];   // score + boxsum per row
__device__ int      g_first_fail;      // min failing row index (init = num)
__device__ float    g_total;
__device__ int      g_count;
__device__ unsigned g_maxbits;         // monotonic-mapped float max
__device__ unsigned g_done;            // block completion counter

__device__ __forceinline__ unsigned f2mono(float f) {
    unsigned b = __float_as_uint(f);
    return (b & 0x80000000u) ? ~b : (b | 0x80000000u);
}
__device__ __forceinline__ float mono2f(unsigned m) {
    return __uint_as_float((m & 0x80000000u) ? (m & 0x7fffffffu) : ~m);
}

__global__ void k_init(int num) {
    g_first_fail = num;
    g_total      = 0.0f;
    g_count      = 0;
    g_maxbits    = 0u;     // below any real float's monotonic code
    g_done       = 0u;
}

// Warp-per-row over rows [0, num): score = rowmax, val = score + sum(box).
// Last block to finish sums g_vals[0..K) where K = min(first_fail, num).
__global__ void k_pass1(const float* __restrict__ post,
                        const float* __restrict__ boxes,
                        int num, int C)
{
    const int lane  = threadIdx.x & 31;
    const int gwarp = (blockIdx.x * blockDim.x + threadIdx.x) >> 5;
    const int nwarp = (gridDim.x * blockDim.x) >> 5;

    for (int row = gwarp; row < num; row += nwarp) {
        float m = -3.4e38f;
        if (C == 80) {
            const float4* p = (const float4*)(post + (size_t)row * 80);
            if (lane < 20) {
                float4 v = __ldg(p + lane);
                m = fmaxf(fmaxf(v.x, v.y), fmaxf(v.z, v.w));
            }
        } else {
            const float* p = post + (size_t)row * C;
            for (int c = lane; c < C; c += 32) m = fmaxf(m, __ldg(p + c));
        }
        #pragma unroll
        for (int off = 16; off; off >>= 1)
            m = fmaxf(m, __shfl_xor_sync(0xffffffffu, m, off));

        if (lane == 0) {
            float4 b = *(const float4*)(boxes + (size_t)row * 4);
            g_vals[row] = m + ((b.x + b.y) + (b.z + b.w));
            if (!(m >= CONF_T)) atomicMin(&g_first_fail, row);
        }
    }

    // --- fused final reduction in the last block to finish (threadfence pattern)
    __shared__ bool is_last;
    __threadfence();
    __syncthreads();
    if (threadIdx.x == 0) {
        unsigned prev = atomicAdd(&g_done, 1u);
        is_last = (prev == gridDim.x - 1);
    }
    __syncthreads();
    if (!is_last) return;

    const int K = g_first_fail;   // final: all blocks have completed
    float s = 0.0f;
    for (int i = threadIdx.x; i < K; i += blockDim.x) s += g_vals[i];

    __shared__ float red[32];
    #pragma unroll
    for (int off = 16; off; off >>= 1) s += __shfl_xor_sync(0xffffffffu, s, off);
    const int wid = threadIdx.x >> 5;
    if (lane == 0) red[wid] = s;
    __syncthreads();
    if (wid == 0) {
        const int nw = blockDim.x >> 5;
        s = (lane < nw) ? red[lane] : 0.0f;
        #pragma unroll
        for (int off = 16; off; off >>= 1) s += __shfl_xor_sync(0xffffffffu, s, off);
        if (lane == 0) { g_total = s; g_count = K; }
    }
}

// Fallback global max over all N*C scores. Early-exits when count > 0
// (the overwhelmingly common case), so live cost = launch overhead only.
__global__ void k_max(const float* __restrict__ post, long long total_elems)
{
    __shared__ int cnt;
    if (threadIdx.x == 0) cnt = g_count;
    __syncthreads();
    if (cnt > 0) return;

    float m = -3.4e38f;
    const long long tid    = (long long)blockIdx.x * blockDim.x + threadIdx.x;
    const long long stride = (long long)gridDim.x * blockDim.x;
    const long long n4     = total_elems >> 2;
    const float4*   p4     = (const float4*)post;
    for (long long i = tid; i < n4; i += stride) {
        float4 v = p4[i];
        m = fmaxf(m, fmaxf(fmaxf(v.x, v.y), fmaxf(v.z, v.w)));
    }
    for (long long i = (n4 << 2) + tid; i < total_elems; i += stride)
        m = fmaxf(m, post[i]);

    #pragma unroll
    for (int off = 16; off; off >>= 1)
        m = fmaxf(m, __shfl_xor_sync(0xffffffffu, m, off));
    if ((threadIdx.x & 31) == 0) atomicMax(&g_maxbits, f2mono(m));
}

__global__ void k_final(float* out)
{
    out[0] = (g_count > 0) ? g_total : mono2f(g_maxbits);
}

extern "C" void kernel_launch(void* const* d_in, const int* in_sizes, int n_in,
                              void* d_out, int out_size)
{
    const float* post  = (const float*)d_in[0];   // [N, C] fp32
    const float* boxes = (const float*)d_in[1];   // [N, 4] fp32
    const long long total = (long long)in_sizes[0];
    const int N = in_sizes[1] / 4;
    const int C = (int)(total / N);

    int num = (int)((double)N * 0.02);
    if (num < 1) num = 1;
    if (num > N) num = N;
    if (num > MAX_NUM) num = MAX_NUM;   // never hit for this shape (num = 20000)

    k_init<<<1, 1>>>(num);

    // warp per row
    const int threads = 256;
    int blocks = (num * 32 + threads - 1) / threads;   // 2500 for num=20000
    k_pass1<<<blocks, threads>>>(post, boxes, num, C);

    k_max<<<296, 256>>>(post, total);

    k_final<<<1, 1>>>((float*)d_out);
}

// round 2
// speedup vs baseline: 1.0010x; 1.0010x over previous
#include <cuda_runtime.h>

// ---------------------------------------------------------------------------
// yolo_detect_target, fully fused single kernel.
// Semantics: num = int(N*0.02); valid = cumprod(score>=0.25 & row<num);
// loss = count>0 ? sum(valid*(score+boxsum)) : max(post).
// Key facts exploited:
//   * only rows [0,num) matter (20000 rows, 6.4MB) unless row 0 fails;
//   * count==0  <=>  row-0 score < CONF (num>=1 always) -> every block can
//     decide the path independently, no grid sync needed;
//   * kernel self-resets its globals in the last block => graph-replayable
//     with static initializers, no init launch.
// ---------------------------------------------------------------------------

#define CONF_T 0.25f
#define MAX_NUM (1 << 20)

__device__ float    g_vals[MAX_NUM];
__device__ int      g_first_fail = 0x7fffffff;  // INT_MAX, reset after use
__device__ unsigned g_maxbits    = 0u;          // monotonic float max
__device__ unsigned g_done       = 0u;          // finished-block counter

__device__ __forceinline__ unsigned f2mono(float f) {
    unsigned b = __float_as_uint(f);
    return (b & 0x80000000u) ? ~b : (b | 0x80000000u);
}
__device__ __forceinline__ float mono2f(unsigned m) {
    return __uint_as_float((m & 0x80000000u) ? (m & 0x7fffffffu) : ~m);
}

__device__ __forceinline__ float warp_max(float m) {
    #pragma unroll
    for (int off = 16; off; off >>= 1)
        m = fmaxf(m, __shfl_xor_sync(0xffffffffu, m, off));
    return m;
}
__device__ __forceinline__ float warp_sum(float s) {
    #pragma unroll
    for (int off = 16; off; off >>= 1)
        s += __shfl_xor_sync(0xffffffffu, s, off);
    return s;
}

__global__ void k_fused(const float* __restrict__ post,
                        const float* __restrict__ boxes,
                        int num, int C, long long total_elems,
                        float* __restrict__ out)
{
    const int lane = threadIdx.x & 31;
    const int wid  = threadIdx.x >> 5;
    __shared__ bool  sh_fallback;
    __shared__ bool  sh_last;
    __shared__ float sh_red[32];

    // ---- path decision: does row 0 pass? (deterministic, same in all blocks)
    if (wid == 0) {
        float m = -3.4e38f;
        if (C == 80) {
            if (lane < 20) {
                float4 v = __ldg((const float4*)post + lane);
                m = fmaxf(fmaxf(v.x, v.y), fmaxf(v.z, v.w));
            }
        } else {
            for (int c = lane; c < C; c += 32) m = fmaxf(m, __ldg(post + c));
        }
        m = warp_max(m);
        if (lane == 0) sh_fallback = !(m >= CONF_T);
    }
    __syncthreads();
    const bool fallback = sh_fallback;

    if (!fallback) {
        // ================= main path: rows [0, num) =================
        const int gwarp = (blockIdx.x * blockDim.x + threadIdx.x) >> 5;
        const int nwarp = (gridDim.x * blockDim.x) >> 5;
        for (int row = gwarp; row < num; row += nwarp) {
            float m = -3.4e38f;
            if (C == 80) {
                if (lane < 20) {
                    float4 v = __ldg((const float4*)(post + (size_t)row * 80) + lane);
                    m = fmaxf(fmaxf(v.x, v.y), fmaxf(v.z, v.w));
                }
            } else {
                const float* p = post + (size_t)row * (size_t)C;
                for (int c = lane; c < C; c += 32) m = fmaxf(m, __ldg(p + c));
            }
            m = warp_max(m);
            if (lane == 0) {
                float4 b = *(const float4*)(boxes + (size_t)row * 4);
                g_vals[row] = m + ((b.x + b.y) + (b.z + b.w));
                if (!(m >= CONF_T)) atomicMin(&g_first_fail, row);
            }
        }
    } else {
        // ================= fallback: global max over all scores =====
        float m = -3.4e38f;
        const long long tid    = (long long)blockIdx.x * blockDim.x + threadIdx.x;
        const long long stride = (long long)gridDim.x * blockDim.x;
        const long long n4     = total_elems >> 2;
        const float4*   p4     = (const float4*)post;
        for (long long i = tid; i < n4; i += stride) {
            float4 v = p4[i];
            m = fmaxf(m, fmaxf(fmaxf(v.x, v.y), fmaxf(v.z, v.w)));
        }
        for (long long i = (n4 << 2) + tid; i < total_elems; i += stride)
            m = fmaxf(m, post[i]);
        m = warp_max(m);
        if (lane == 0) atomicMax(&g_maxbits, f2mono(m));
    }

    // ---- last-block finalize (threadfence reduction pattern)
    __threadfence();
    __syncthreads();
    if (threadIdx.x == 0) {
        unsigned prev = atomicAdd(&g_done, 1u);
        sh_last = (prev == gridDim.x - 1);
    }
    __syncthreads();
    if (!sh_last) return;

    if (!fallback) {
        int K = g_first_fail;
        if (K > num) K = num;           // INT_MAX sentinel -> num
        float s = 0.0f;
        for (int i = threadIdx.x; i < K; i += blockDim.x) s += g_vals[i];
        s = warp_sum(s);
        if (lane == 0) sh_red[wid] = s;
        __syncthreads();
        if (wid == 0) {
            const int nw = blockDim.x >> 5;
            s = (lane < nw) ? sh_red[lane] : 0.0f;
            s = warp_sum(s);
            if (lane == 0) out[0] = s;  // K >= 1 guaranteed on this path
        }
    } else {
        if (threadIdx.x == 0) out[0] = mono2f(g_maxbits);
    }

    // ---- self-reset for next graph replay
    if (threadIdx.x == 0) {
        g_first_fail = 0x7fffffff;
        g_maxbits    = 0u;
        g_done       = 0u;
    }
}

extern "C" void kernel_launch(void* const* d_in, const int* in_sizes, int n_in,
                              void* d_out, int out_size)
{
    const float* post  = (const float*)d_in[0];   // [N, C] fp32
    const float* boxes = (const float*)d_in[1];   // [N, 4] fp32
    const long long total = (long long)in_sizes[0];
    const int N = in_sizes[1] / 4;
    const int C = (int)(total / N);

    int num = (int)((double)N * 0.02);
    if (num < 1) num = 1;
    if (num > N) num = N;
    if (num > MAX_NUM) num = MAX_NUM;   // not hit for this shape (num = 20000)

    const int threads = 256;
    int blocks = (num * 32 + threads - 1) / threads;   // 2500 for num=20000
    if (blocks < 1) blocks = 1;
    k_fused<<<blocks, threads>>>(post, boxes, num, C, total, (float*)d_out);
}

// round 3
// speedup vs baseline: 3.2446x; 3.2415x over previous
#include <cuda_runtime.h>

// ---------------------------------------------------------------------------
// yolo_detect_target — single kernel, thread-per-row, latency-optimized.
// num = int(N*0.02) = 20000 rows are the only ones that can contribute.
// Common case (no row fails conf): answer = sum of 79 per-block partials.
// Rare cases (early break / row-0 fail -> global max) handled correctly
// but off the hot path.
// ---------------------------------------------------------------------------

#define CONF_T  0.25f
#define THREADS 256
#define MAX_NUM (1 << 20)
#define MAX_BLK 4096

__device__ float    g_vals[MAX_NUM];            // per-row value (rare-path use)
__device__ float    g_bsum[MAX_BLK];            // per-block partial sums
__device__ int      g_first_fail = 0x7fffffff;  // reset by last block
__device__ unsigned g_maxbits    = 0u;
__device__ unsigned g_done       = 0u;

__device__ __forceinline__ unsigned f2mono(float f) {
    unsigned b = __float_as_uint(f);
    return (b & 0x80000000u) ? ~b : (b | 0x80000000u);
}
__device__ __forceinline__ float mono2f(unsigned m) {
    return __uint_as_float((m & 0x80000000u) ? (m & 0x7fffffffu) : ~m);
}
__device__ __forceinline__ float warp_max(float m) {
    #pragma unroll
    for (int off = 16; off; off >>= 1)
        m = fmaxf(m, __shfl_xor_sync(0xffffffffu, m, off));
    return m;
}
__device__ __forceinline__ float warp_sum(float s) {
    #pragma unroll
    for (int off = 16; off; off >>= 1)
        s += __shfl_xor_sync(0xffffffffu, s, off);
    return s;
}

__global__ __launch_bounds__(THREADS)
void k_fused(const float* __restrict__ post,
             const float* __restrict__ boxes,
             int num, int C, long long total_elems,
             float* __restrict__ out)
{
    const int lane = threadIdx.x & 31;
    const int wid  = threadIdx.x >> 5;
    __shared__ bool  sh_fallback;
    __shared__ bool  sh_last;
    __shared__ float sh_red[THREADS / 32];

    // ---- path decision: row 0 pass/fail (identical result in every block)
    if (wid == 0) {
        float m = -3.4e38f;
        if (C == 80) {
            if (lane < 20) {
                float4 v = __ldg((const float4*)post + lane);
                m = fmaxf(fmaxf(v.x, v.y), fmaxf(v.z, v.w));
            }
        } else {
            for (int c = lane; c < C; c += 32) m = fmaxf(m, __ldg(post + c));
        }
        m = warp_max(m);
        if (lane == 0) sh_fallback = !(m >= CONF_T);
    }
    __syncthreads();
    const bool fallback = sh_fallback;

    if (!fallback) {
        // ============ hot path: thread-per-row, MLP=20 ============
        const int row = blockIdx.x * THREADS + threadIdx.x;
        float val = 0.0f;
        if (row < num) {
            float m = -3.4e38f;
            if (C == 80) {
                const float4* p = (const float4*)(post + (size_t)row * 80);
                #pragma unroll
                for (int i = 0; i < 20; i++) {
                    float4 v = __ldg(p + i);
                    m = fmaxf(m, fmaxf(fmaxf(v.x, v.y), fmaxf(v.z, v.w)));
                }
            } else {
                const float* p = post + (size_t)row * (size_t)C;
                for (int c = 0; c < C; c++) m = fmaxf(m, __ldg(p + c));
            }
            float4 b = __ldg((const float4*)boxes + row);
            val = m + ((b.x + b.y) + (b.z + b.w));
            g_vals[row] = val;                       // rare-path material
            if (!(m >= CONF_T)) atomicMin(&g_first_fail, row);
        }
        // deterministic block sum
        float s = warp_sum(val);
        if (lane == 0) sh_red[wid] = s;
        __syncthreads();
        if (wid == 0) {
            s = (lane < THREADS / 32) ? sh_red[lane] : 0.0f;
            s = warp_sum(s);
            if (lane == 0) g_bsum[blockIdx.x] = s;
        }
    } else {
        // ============ rare: global max over all scores ============
        float m = -3.4e38f;
        const long long tid    = (long long)blockIdx.x * blockDim.x + threadIdx.x;
        const long long stride = (long long)gridDim.x * blockDim.x;
        const long long n4     = total_elems >> 2;
        const float4*   p4     = (const float4*)post;
        for (long long i = tid; i < n4; i += stride) {
            float4 v = p4[i];
            m = fmaxf(m, fmaxf(fmaxf(v.x, v.y), fmaxf(v.z, v.w)));
        }
        for (long long i = (n4 << 2) + tid; i < total_elems; i += stride)
            m = fmaxf(m, post[i]);
        m = warp_max(m);
        if (lane == 0) atomicMax(&g_maxbits, f2mono(m));
    }

    // ---- last-block finalize
    __threadfence();
    __syncthreads();
    if (threadIdx.x == 0) {
        unsigned prev = atomicAdd(&g_done, 1u);
        sh_last = (prev == gridDim.x - 1);
    }
    __syncthreads();
    if (!sh_last) return;

    if (!fallback) {
        int K = g_first_fail;
        if (K >= num) {
            // common case: sum the (few) per-block partials, fixed order
            float s = 0.0f;
            for (int i = threadIdx.x; i < (int)gridDim.x; i += THREADS)
                s += g_bsum[i];
            s = warp_sum(s);
            if (lane == 0) sh_red[wid] = s;
            __syncthreads();
            if (wid == 0) {
                s = (lane < THREADS / 32) ? sh_red[lane] : 0.0f;
                s = warp_sum(s);
                if (lane == 0) out[0] = s;
            }
        } else {
            // rare: early break at K -> direct sum of g_vals[0..K)
            float s = 0.0f;
            for (int i = threadIdx.x; i < K; i += THREADS) s += g_vals[i];
            s = warp_sum(s);
            if (lane == 0) sh_red[wid] = s;
            __syncthreads();
            if (wid == 0) {
                s = (lane < THREADS / 32) ? sh_red[lane] : 0.0f;
                s = warp_sum(s);
                if (lane == 0) out[0] = s;   // K >= 1 on this path
            }
        }
    } else {
        if (threadIdx.x == 0) out[0] = mono2f(g_maxbits);
    }

    // ---- self-reset for next graph replay
    __syncthreads();
    if (threadIdx.x == 0) {
        g_first_fail = 0x7fffffff;
        g_maxbits    = 0u;
        g_done       = 0u;
    }
}

extern "C" void kernel_launch(void* const* d_in, const int* in_sizes, int n_in,
                              void* d_out, int out_size)
{
    const float* post  = (const float*)d_in[0];   // [N, C] fp32
    const float* boxes = (const float*)d_in[1];   // [N, 4] fp32
    const long long total = (long long)in_sizes[0];
    const int N = in_sizes[1] / 4;
    const int C = (int)(total / N);

    int num = (int)((double)N * 0.02);
    if (num < 1) num = 1;
    if (num > N) num = N;
    if (num > MAX_NUM) num = MAX_NUM;

    int blocks = (num + THREADS - 1) / THREADS;   // 79 for num=20000
    if (blocks > MAX_BLK) blocks = MAX_BLK;       // not hit for this shape
    k_fused<<<blocks, THREADS>>>(post, boxes, num, C, total, (float*)d_out);
}

// round 4
// speedup vs baseline: 3.3916x; 1.0453x over previous
#include <cuda_runtime.h>

// ---------------------------------------------------------------------------
// yolo_detect_target — one kernel, thread-per-row, no pre-check, no hot-path
// global stores. Deterministic order-independent sum via int64 fixed point
// (scale 2^32). Rare paths (early break / row-0 fail) run in the last block
// only — correct but off the timed path.
// ---------------------------------------------------------------------------

#define CONF_T  0.25f
#define THREADS 256
#define FXSCALE 4294967296.0   // 2^32

__device__ unsigned long long g_fx         = 0ull;         // fixed-point total
__device__ int                g_first_fail = 0x7fffffff;
__device__ unsigned           g_done       = 0u;

__device__ __forceinline__ float warp_max(float m) {
    #pragma unroll
    for (int off = 16; off; off >>= 1)
        m = fmaxf(m, __shfl_xor_sync(0xffffffffu, m, off));
    return m;
}
__device__ __forceinline__ float warp_sum(float s) {
    #pragma unroll
    for (int off = 16; off; off >>= 1)
        s += __shfl_xor_sync(0xffffffffu, s, off);
    return s;
}

// row score (max over C) for one row, computed by one thread
__device__ __forceinline__ float row_max(const float* __restrict__ post,
                                         int row, int C) {
    float m = -3.4e38f;
    if (C == 80) {
        const float4* p = (const float4*)(post + (size_t)row * 80);
        #pragma unroll
        for (int i = 0; i < 20; i++) {
            float4 v = __ldg(p + i);
            m = fmaxf(m, fmaxf(fmaxf(v.x, v.y), fmaxf(v.z, v.w)));
        }
    } else {
        const float* p = post + (size_t)row * (size_t)C;
        for (int c = 0; c < C; c++) m = fmaxf(m, __ldg(p + c));
    }
    return m;
}

__global__ __launch_bounds__(THREADS)
void k_fused(const float* __restrict__ post,
             const float* __restrict__ boxes,
             int num, int C, long long total_elems,
             float* __restrict__ out)
{
    const int lane = threadIdx.x & 31;
    const int wid  = threadIdx.x >> 5;
    __shared__ bool  sh_last;
    __shared__ float sh_red[THREADS / 32];

    // ============ hot path: thread-per-row, loads issue immediately ========
    const int row = blockIdx.x * THREADS + threadIdx.x;
    float val = 0.0f;
    if (row < num) {
        float m = row_max(post, row, C);
        float4 b = __ldg((const float4*)boxes + row);
        val = m + ((b.x + b.y) + (b.z + b.w));
        if (!(m >= CONF_T)) atomicMin(&g_first_fail, row);
    }
    // warp sum (fixed order -> deterministic), then integer atomic (commutes)
    float s = warp_sum(val);
    if (lane == 0) {
        long long fx = __double2ll_rn((double)s * FXSCALE);
        atomicAdd(&g_fx, (unsigned long long)fx);
    }

    // ---- completion counter
    __threadfence();
    __syncthreads();
    if (threadIdx.x == 0)
        sh_last = (atomicAdd(&g_done, 1u) == gridDim.x - 1);
    __syncthreads();
    if (!sh_last) return;

    // ================= last block: finalize ================================
    const int K = (g_first_fail < num) ? g_first_fail : num;

    if (K >= num) {
        // common case: total already accumulated
        if (threadIdx.x == 0)
            out[0] = (float)((double)(long long)g_fx / FXSCALE);
    } else if (K == 0) {
        // rare: row 0 failed -> loss = max over ALL of post (last block alone)
        float m = -3.4e38f;
        const long long n4 = total_elems >> 2;
        const float4* p4 = (const float4*)post;
        for (long long i = threadIdx.x; i < n4; i += THREADS) {
            float4 v = p4[i];
            m = fmaxf(m, fmaxf(fmaxf(v.x, v.y), fmaxf(v.z, v.w)));
        }
        for (long long i = (n4 << 2) + threadIdx.x; i < total_elems; i += THREADS)
            m = fmaxf(m, post[i]);
        m = warp_max(m);
        if (lane == 0) sh_red[wid] = m;
        __syncthreads();
        if (wid == 0) {
            m = (lane < THREADS / 32) ? sh_red[lane] : -3.4e38f;
            m = warp_max(m);
            if (lane == 0) out[0] = m;
        }
    } else {
        // rare: early break at K -> recompute sum over rows [0, K)
        float s2 = 0.0f;
        for (int r = threadIdx.x; r < K; r += THREADS) {
            float m = row_max(post, r, C);
            float4 b = __ldg((const float4*)boxes + r);
            s2 += m + ((b.x + b.y) + (b.z + b.w));
        }
        s2 = warp_sum(s2);
        if (lane == 0) sh_red[wid] = s2;
        __syncthreads();
        if (wid == 0) {
            s2 = (lane < THREADS / 32) ? sh_red[lane] : 0.0f;
            s2 = warp_sum(s2);
            if (lane == 0) out[0] = s2;
        }
    }

    // ---- self-reset for next graph replay
    __syncthreads();
    if (threadIdx.x == 0) {
        g_fx         = 0ull;
        g_first_fail = 0x7fffffff;
        g_done       = 0u;
    }
}

extern "C" void kernel_launch(void* const* d_in, const int* in_sizes, int n_in,
                              void* d_out, int out_size)
{
    const float* post  = (const float*)d_in[0];   // [N, C] fp32
    const float* boxes = (const float*)d_in[1];   // [N, 4] fp32
    const long long total = (long long)in_sizes[0];
    const int N = in_sizes[1] / 4;
    const int C = (int)(total / N);

    int num = (int)((double)N * 0.02);
    if (num < 1) num = 1;
    if (num > N) num = N;

    int blocks = (num + THREADS - 1) / THREADS;   // 79 for num=20000
    k_fused<<<blocks, THREADS>>>(post, boxes, num, C, total, (float*)d_out);
}

// round 5
// speedup vs baseline: 3.8529x; 1.1360x over previous
#include <cuda_runtime.h>

// ---------------------------------------------------------------------------
// yolo_detect_target — coalesced two-phase kernel.
// Phase 1: block loads 128 rows (2560 float4 chunks) fully coalesced,
//          per-chunk max -> smem (padded, conflict-free).
// Phase 2: thread-per-row reduces 20 chunk-maxes + box sum; deterministic
//          fixed-point atomic total. Rare paths (early conf break, row-0
//          fail -> global max) handled in the last block off the hot path.
// ---------------------------------------------------------------------------

#define CONF_T   0.25f
#define THREADS  256
#define ROWS_PB  128
#define CPR      20                  // float4 chunks per row (C=80)
#define CHUNKS_PB (ROWS_PB * CPR)    // 2560
#define FXSCALE  4294967296.0        // 2^32

__device__ unsigned long long g_fx         = 0ull;
__device__ int                g_first_fail = 0x7fffffff;
__device__ unsigned           g_done       = 0u;

__device__ __forceinline__ float warp_max(float m) {
    #pragma unroll
    for (int off = 16; off; off >>= 1)
        m = fmaxf(m, __shfl_xor_sync(0xffffffffu, m, off));
    return m;
}
__device__ __forceinline__ float warp_sum(float s) {
    #pragma unroll
    for (int off = 16; off; off >>= 1)
        s += __shfl_xor_sync(0xffffffffu, s, off);
    return s;
}

// single-thread row max over C columns (rare-path / generic use)
__device__ __forceinline__ float row_max(const float* __restrict__ post,
                                         int row, int C) {
    float m = -3.4e38f;
    if (C == 80) {
        const float4* p = (const float4*)(post + (size_t)row * 80);
        #pragma unroll
        for (int i = 0; i < 20; i++) {
            float4 v = __ldg(p + i);
            m = fmaxf(m, fmaxf(fmaxf(v.x, v.y), fmaxf(v.z, v.w)));
        }
    } else {
        const float* p = post + (size_t)row * (size_t)C;
        for (int c = 0; c < C; c++) m = fmaxf(m, __ldg(p + c));
    }
    return m;
}

__global__ __launch_bounds__(THREADS)
void k_fused(const float* __restrict__ post,
             const float* __restrict__ boxes,
             int num, int C, long long total_elems,
             float* __restrict__ out)
{
    const int lane = threadIdx.x & 31;
    const int wid  = threadIdx.x >> 5;
    __shared__ float cmax[ROWS_PB * (CPR + 1)];   // pad 21 -> conflict-free
    __shared__ bool  sh_last;
    __shared__ float sh_red[THREADS / 32];

    float val = 0.0f;

    if (C == 80) {
        // ---- phase 1: coalesced chunk loads + per-chunk max --------------
        const float4* p4   = (const float4*)post;
        const long long base = (long long)blockIdx.x * CHUNKS_PB;
        const long long lim  = (long long)num * CPR;
        #pragma unroll
        for (int i = 0; i < CHUNKS_PB / THREADS; i++) {
            int lc = i * THREADS + threadIdx.x;        // 0..2559
            long long g = base + lc;
            if (g < lim) {
                float4 v = __ldg(p4 + g);
                float m3 = fmaxf(fmaxf(v.x, v.y), fmaxf(v.z, v.w));
                int r = lc / CPR;
                int c = lc - r * CPR;
                cmax[r * (CPR + 1) + c] = m3;
            }
        }
        __syncthreads();

        // ---- phase 2: thread-per-row reduce from smem --------------------
        const int row = blockIdx.x * ROWS_PB + threadIdx.x;
        if (threadIdx.x < ROWS_PB && row < num) {
            const float* cm = &cmax[threadIdx.x * (CPR + 1)];
            float m = cm[0];
            #pragma unroll
            for (int c = 1; c < CPR; c++) m = fmaxf(m, cm[c]);
            float4 b = __ldg((const float4*)boxes + row);
            val = m + ((b.x + b.y) + (b.z + b.w));
            if (!(m >= CONF_T)) atomicMin(&g_first_fail, row);
        }
    } else {
        // generic path (not hit for this shape)
        const int row = blockIdx.x * ROWS_PB + threadIdx.x;
        if (threadIdx.x < ROWS_PB && row < num) {
            float m = row_max(post, row, C);
            float4 b = __ldg((const float4*)boxes + row);
            val = m + ((b.x + b.y) + (b.z + b.w));
            if (!(m >= CONF_T)) atomicMin(&g_first_fail, row);
        }
    }

    // ---- deterministic accumulate (warps holding rows only) --------------
    float s = warp_sum(val);
    if (lane == 0 && wid * 32 < ROWS_PB) {
        long long fx = __double2ll_rn((double)s * FXSCALE);
        atomicAdd(&g_fx, (unsigned long long)fx);
    }

    // ---- completion counter ---------------------------------------------
    __threadfence();
    __syncthreads();
    if (threadIdx.x == 0)
        sh_last = (atomicAdd(&g_done, 1u) == gridDim.x - 1);
    __syncthreads();
    if (!sh_last) return;

    // ================= last block: finalize ===============================
    const int K = (g_first_fail < num) ? g_first_fail : num;

    if (K >= num) {
        if (threadIdx.x == 0)
            out[0] = (float)((double)(long long)g_fx / FXSCALE);
    } else if (K == 0) {
        // rare: row 0 failed -> loss = max over all of post
        float m = -3.4e38f;
        const long long n4 = total_elems >> 2;
        const float4* p4 = (const float4*)post;
        for (long long i = threadIdx.x; i < n4; i += THREADS) {
            float4 v = p4[i];
            m = fmaxf(m, fmaxf(fmaxf(v.x, v.y), fmaxf(v.z, v.w)));
        }
        for (long long i = (n4 << 2) + threadIdx.x; i < total_elems; i += THREADS)
            m = fmaxf(m, post[i]);
        m = warp_max(m);
        if (lane == 0) sh_red[wid] = m;
        __syncthreads();
        if (wid == 0) {
            m = (lane < THREADS / 32) ? sh_red[lane] : -3.4e38f;
            m = warp_max(m);
            if (lane == 0) out[0] = m;
        }
    } else {
        // rare: early break at K -> recompute sum over rows [0, K)
        float s2 = 0.0f;
        for (int r = threadIdx.x; r < K; r += THREADS) {
            float m = row_max(post, r, C);
            float4 b = __ldg((const float4*)boxes + r);
            s2 += m + ((b.x + b.y) + (b.z + b.w));
        }
        s2 = warp_sum(s2);
        if (lane == 0) sh_red[wid] = s2;
        __syncthreads();
        if (wid == 0) {
            s2 = (lane < THREADS / 32) ? sh_red[lane] : 0.0f;
            s2 = warp_sum(s2);
            if (lane == 0) out[0] = s2;
        }
    }

    // ---- self-reset for next graph replay --------------------------------
    __syncthreads();
    if (threadIdx.x == 0) {
        g_fx         = 0ull;
        g_first_fail = 0x7fffffff;
        g_done       = 0u;
    }
}

extern "C" void kernel_launch(void* const* d_in, const int* in_sizes, int n_in,
                              void* d_out, int out_size)
{
    const float* post  = (const float*)d_in[0];   // [N, C] fp32
    const float* boxes = (const float*)d_in[1];   // [N, 4] fp32
    const long long total = (long long)in_sizes[0];
    const int N = in_sizes[1] / 4;
    const int C = (int)(total / N);

    int num = (int)((double)N * 0.02);
    if (num < 1) num = 1;
    if (num > N) num = N;

    int blocks = (num + ROWS_PB - 1) / ROWS_PB;   // 157 for num=20000
    k_fused<<<blocks, THREADS>>>(post, boxes, num, C, total, (float*)d_out);
}